// round 11
// baseline (speedup 1.0000x reference)
#include <cuda_runtime.h>
#include <cuda_bf16.h>
#include <math_constants.h>

// Collapsed model:
//   out[b,n,e] = cd[b,n]*u[e] + density[b,n]*v[e] + c[e]
// Single kernel. Block 0 / warp 0 computes u/v/c and publishes via flag;
// every other warp is fully autonomous (load -> centroid -> 3NN) and only
// polls the flag right before its store epilogue.

__device__ float g_u[128];
__device__ float g_v[128];
__device__ float g_c[128];
__device__ volatile unsigned g_flag = 0;
__device__ unsigned g_done = 0;

#define D3   42
#define NPT  49
#define EOUT 128

__global__ __launch_bounds__(256)
void nrpf_one(const float* __restrict__ points,
              const float* __restrict__ W_dist,
              const float* __restrict__ b_dist,
              const float* __restrict__ emb,
              const float* __restrict__ W_den,
              const float* __restrict__ b_den,
              const float* __restrict__ W_out,
              const float* __restrict__ b_out,
              float* __restrict__ out,
              int nbatch) {
    const int lane = threadIdx.x & 31;
    const int wid  = threadIdx.x >> 5;
    const int batch = blockIdx.x * 8 + wid;
    const bool active = batch < nbatch;

    __shared__ float4 s_pq[8][NPT];     // {x,y,z,|p|^2} per warp slab
    __shared__ float2 s_cddn[8][NPT];   // {centroid_dist, density}

    // ---- block 0 / warp 0: compute u/v/c, publish ----
    if (blockIdx.x == 0 && wid == 0) {
        // lane owns e = 4*lane .. 4*lane+3  (one float4 column)
        float4 u = make_float4(0.f, 0.f, 0.f, 0.f);
        float4 v = u, c = u;
#pragma unroll 6
        for (int d = 0; d < D3; d++) {
            float wd = W_dist[d];
            float bd = b_dist[d];
            float em = emb[NPT * D3 + d];
            float wn = W_den[d];
            float bn = b_den[d];
            float4 wo0 = reinterpret_cast<const float4*>(W_out + d * EOUT)[lane];
            float4 wo1 = reinterpret_cast<const float4*>(W_out + (D3 + d) * EOUT)[lane];
            float4 wo2 = reinterpret_cast<const float4*>(W_out + (2 * D3 + d) * EOUT)[lane];
            u.x = fmaf(wd, wo0.x, u.x); u.y = fmaf(wd, wo0.y, u.y);
            u.z = fmaf(wd, wo0.z, u.z); u.w = fmaf(wd, wo0.w, u.w);
            v.x = fmaf(wn, wo2.x, v.x); v.y = fmaf(wn, wo2.y, v.y);
            v.z = fmaf(wn, wo2.z, v.z); v.w = fmaf(wn, wo2.w, v.w);
            c.x = fmaf(bd, wo0.x, fmaf(em, wo1.x, fmaf(bn, wo2.x, c.x)));
            c.y = fmaf(bd, wo0.y, fmaf(em, wo1.y, fmaf(bn, wo2.y, c.y)));
            c.z = fmaf(bd, wo0.z, fmaf(em, wo1.z, fmaf(bn, wo2.z, c.z)));
            c.w = fmaf(bd, wo0.w, fmaf(em, wo1.w, fmaf(bn, wo2.w, c.w)));
        }
        float4 bo = reinterpret_cast<const float4*>(b_out)[lane];
        c.x += bo.x; c.y += bo.y; c.z += bo.z; c.w += bo.w;
        reinterpret_cast<float4*>(g_u)[lane] = u;
        reinterpret_cast<float4*>(g_v)[lane] = v;
        reinterpret_cast<float4*>(g_c)[lane] = c;
        __threadfence();
        __syncwarp();
        if (lane == 0) g_flag = 1u;
    }

    // ---- warp-autonomous per-batch work ----
    if (active) {
        const float* pb = points + (size_t)batch * (NPT * 3);

        const int  n0   = lane;
        const int  n1   = lane + 32;
        const bool has1 = (n1 < NPT);

        float x0 = pb[n0 * 3 + 0], y0 = pb[n0 * 3 + 1], z0 = pb[n0 * 3 + 2];
        float x1 = 0.f, y1 = 0.f, z1 = 0.f;
        if (has1) { x1 = pb[n1 * 3 + 0]; y1 = pb[n1 * 3 + 1]; z1 = pb[n1 * 3 + 2]; }

        float w0 = fmaf(x0, x0, fmaf(y0, y0, z0 * z0));
        float w1 = fmaf(x1, x1, fmaf(y1, y1, z1 * z1));
        s_pq[wid][n0] = make_float4(x0, y0, z0, w0);
        if (has1) s_pq[wid][n1] = make_float4(x1, y1, z1, w1);
        __syncwarp();

        // centroid via butterfly shuffle
        float sx = x0 + x1, sy = y0 + y1, sz = z0 + z1;
#pragma unroll
        for (int o = 16; o > 0; o >>= 1) {
            sx += __shfl_xor_sync(0xFFFFFFFFu, sx, o);
            sy += __shfl_xor_sync(0xFFFFFFFFu, sy, o);
            sz += __shfl_xor_sync(0xFFFFFFFFu, sz, o);
        }
        const float cx = sx * (1.0f / 49.0f);
        const float cy = sy * (1.0f / 49.0f);
        const float cz = sz * (1.0f / 49.0f);

        float dx = x0 - cx, dy = y0 - cy, dz = z0 - cz;
        float cd0 = sqrtf(fmaf(dx, dx, fmaf(dy, dy, dz * dz)));
        dx = x1 - cx; dy = y1 - cy; dz = z1 - cz;
        float cd1 = sqrtf(fmaf(dx, dx, fmaf(dy, dy, dz * dz)));

        // 3-NN: one smem sweep serves both owned points
        float a0 = CUDART_INF_F, a1 = CUDART_INF_F, a2 = CUDART_INF_F;
        float b0 = CUDART_INF_F, b1 = CUDART_INF_F, b2 = CUDART_INF_F;
#pragma unroll 7
        for (int m = 0; m < NPT; m++) {
            float4 p = s_pq[wid][m];                 // broadcast LDS.128
            float dot = fmaf(x0, p.x, fmaf(y0, p.y, z0 * p.z));
            float d2  = fmaxf(fmaf(-2.f, dot, w0 + p.w), 0.f);
            d2 = (m == n0) ? CUDART_INF_F : d2;
            float t0 = fmaxf(a0, d2);  a0 = fminf(a0, d2);
            float t1 = fmaxf(a1, t0);  a1 = fminf(a1, t0);
            a2 = fminf(a2, t1);
            dot = fmaf(x1, p.x, fmaf(y1, p.y, z1 * p.z));
            d2  = fmaxf(fmaf(-2.f, dot, w1 + p.w), 0.f);
            d2 = (m == n1) ? CUDART_INF_F : d2;
            t0 = fmaxf(b0, d2);  b0 = fminf(b0, d2);
            t1 = fmaxf(b1, t0);  b1 = fminf(b1, t0);
            b2 = fminf(b2, t1);
        }
        float dn0 = (sqrtf(a0) + sqrtf(a1) + sqrtf(a2)) * (1.0f / 3.0f);
        s_cddn[wid][n0] = make_float2(cd0, dn0);
        if (has1) {
            float dn1 = (sqrtf(b0) + sqrtf(b1) + sqrtf(b2)) * (1.0f / 3.0f);
            s_cddn[wid][n1] = make_float2(cd1, dn1);
        }
        __syncwarp();
    }

    // ---- acquire u/v/c (flag set long ago for almost every warp) ----
    if (lane == 0) {
        while (g_flag == 0u) { __nanosleep(64); }
    }
    __syncwarp();
    __threadfence();   // acquire: order g_u/g_v/g_c loads after flag observe

    const float4 ru = reinterpret_cast<const float4*>(g_u)[lane];
    const float4 rv = reinterpret_cast<const float4*>(g_v)[lane];
    const float4 rc = reinterpret_cast<const float4*>(g_c)[lane];

    // ---- epilogue: 49 rows x 128 floats, lane stores its float4 column ----
    if (active) {
        float4* outp = reinterpret_cast<float4*>(out)
                     + (size_t)batch * (NPT * 32) + lane;
#pragma unroll 7
        for (int r = 0; r < NPT; r++) {
            float2 cddn = s_cddn[wid][r];            // broadcast LDS.64
            float4 o;
            o.x = fmaf(cddn.x, ru.x, fmaf(cddn.y, rv.x, rc.x));
            o.y = fmaf(cddn.x, ru.y, fmaf(cddn.y, rv.y, rc.y));
            o.z = fmaf(cddn.x, ru.z, fmaf(cddn.y, rv.z, rc.z));
            o.w = fmaf(cddn.x, ru.w, fmaf(cddn.y, rv.w, rc.w));
            outp[(size_t)r * 32] = o;
        }
    }

    // ---- reset flags for next graph replay (last block, after all work) ----
    __syncthreads();
    if (threadIdx.x == 0) {
        unsigned d = atomicAdd(&g_done, 1u);
        if (d == gridDim.x - 1) {
            g_done = 0u;
            g_flag = 0u;
        }
    }
}

extern "C" void kernel_launch(void* const* d_in, const int* in_sizes, int n_in,
                              void* d_out, int out_size) {
    const float* points = (const float*)d_in[0];
    const float* W_dist = (const float*)d_in[1];
    const float* b_dist = (const float*)d_in[2];
    const float* emb    = (const float*)d_in[3];
    const float* W_den  = (const float*)d_in[4];
    const float* b_den  = (const float*)d_in[5];
    const float* W_out  = (const float*)d_in[6];
    const float* b_out  = (const float*)d_in[7];
    float* out = (float*)d_out;

    int B = in_sizes[0] / (NPT * 3);
    int grid = (B + 7) / 8;

    nrpf_one<<<grid, 256>>>(points, W_dist, b_dist, emb, W_den, b_den,
                            W_out, b_out, out, B);
}

// round 12
// speedup vs baseline: 2.5982x; 2.5982x over previous
#include <cuda_runtime.h>
#include <cuda_bf16.h>
#include <math_constants.h>

// Collapsed model:
//   out[b,n,e] = cd[b,n]*u[e] + density[b,n]*v[e] + c[e]
// u/v/c by a 1-block precompute kernel, overlapped via PDL.
// Main kernel: ONE WARP PER BATCH, no __syncthreads; output written with
// streaming (evict-first) stores since it is write-once and 205MB >> L2.

__device__ float g_u[128];
__device__ float g_v[128];
__device__ float g_c[128];

#define D3   42
#define NPT  49
#define EOUT 128

// ---------------------------------------------------------------------------
__global__ __launch_bounds__(1024)
void precompute_uvc(const float* __restrict__ W_dist,
                    const float* __restrict__ b_dist,
                    const float* __restrict__ emb,
                    const float* __restrict__ W_den,
                    const float* __restrict__ b_den,
                    const float* __restrict__ W_out,
                    const float* __restrict__ b_out) {
    cudaTriggerProgrammaticLaunchCompletion();

    __shared__ float su[8][128], sv[8][128], sc[8][128];
    int t = threadIdx.x;
    int e = t & 127;
    int s = t >> 7;
    float u = 0.f, v = 0.f, c = 0.f;
    for (int d = s; d < D3; d += 8) {
        float wo0 = W_out[d * EOUT + e];
        float wo1 = W_out[(D3 + d) * EOUT + e];
        float wo2 = W_out[(2 * D3 + d) * EOUT + e];
        u = fmaf(W_dist[d], wo0, u);
        v = fmaf(W_den[d], wo2, v);
        c = fmaf(b_dist[d], wo0, c);
        c = fmaf(emb[NPT * D3 + d], wo1, c);
        c = fmaf(b_den[d], wo2, c);
    }
    su[s][e] = u; sv[s][e] = v; sc[s][e] = c;
    __syncthreads();
    if (s == 0) {
        float U = 0.f, V = 0.f, C = 0.f;
#pragma unroll
        for (int k = 0; k < 8; k++) { U += su[k][e]; V += sv[k][e]; C += sc[k][e]; }
        g_u[e] = U;
        g_v[e] = V;
        g_c[e] = C + b_out[e];
    }
}

// ---------------------------------------------------------------------------
// Main: warp w of block b owns batch  bid*8 + w.  8 warps / 256 threads.
// ---------------------------------------------------------------------------
__global__ __launch_bounds__(256)
void nrpf_main(const float* __restrict__ points, float* __restrict__ out,
               int nbatch) {
    const int lane = threadIdx.x & 31;
    const int wid  = threadIdx.x >> 5;
    const int batch = blockIdx.x * 8 + wid;
    const bool active = batch < nbatch;

    __shared__ float4 s_pq[8][NPT];     // {x,y,z,|p|^2} per warp slab
    __shared__ float2 s_cddn[8][NPT];   // {centroid_dist, density}

    if (active) {
        const float* pb = points + (size_t)batch * (NPT * 3);

        // ---- load points: lane owns n0 = lane, n1 = lane+32 (if <49) ----
        const int  n0   = lane;
        const int  n1   = lane + 32;
        const bool has1 = (n1 < NPT);

        float x0 = pb[n0 * 3 + 0], y0 = pb[n0 * 3 + 1], z0 = pb[n0 * 3 + 2];
        float x1 = 0.f, y1 = 0.f, z1 = 0.f;
        if (has1) { x1 = pb[n1 * 3 + 0]; y1 = pb[n1 * 3 + 1]; z1 = pb[n1 * 3 + 2]; }

        float w0 = fmaf(x0, x0, fmaf(y0, y0, z0 * z0));
        float w1 = fmaf(x1, x1, fmaf(y1, y1, z1 * z1));
        s_pq[wid][n0] = make_float4(x0, y0, z0, w0);
        if (has1) s_pq[wid][n1] = make_float4(x1, y1, z1, w1);
        __syncwarp();

        // ---- centroid via butterfly shuffle reduce ----
        float sx = x0 + x1, sy = y0 + y1, sz = z0 + z1;
#pragma unroll
        for (int o = 16; o > 0; o >>= 1) {
            sx += __shfl_xor_sync(0xFFFFFFFFu, sx, o);
            sy += __shfl_xor_sync(0xFFFFFFFFu, sy, o);
            sz += __shfl_xor_sync(0xFFFFFFFFu, sz, o);
        }
        const float cx = sx * (1.0f / 49.0f);
        const float cy = sy * (1.0f / 49.0f);
        const float cz = sz * (1.0f / 49.0f);

        float dx = x0 - cx, dy = y0 - cy, dz = z0 - cz;
        float cd0 = sqrtf(fmaf(dx, dx, fmaf(dy, dy, dz * dz)));
        dx = x1 - cx; dy = y1 - cy; dz = z1 - cz;
        float cd1 = sqrtf(fmaf(dx, dx, fmaf(dy, dy, dz * dz)));

        // ---- 3-NN: one smem sweep serves both owned points ----
        float a0 = CUDART_INF_F, a1 = CUDART_INF_F, a2 = CUDART_INF_F;
        float b0 = CUDART_INF_F, b1 = CUDART_INF_F, b2 = CUDART_INF_F;
#pragma unroll 7
        for (int m = 0; m < NPT; m++) {
            float4 p = s_pq[wid][m];                 // broadcast LDS.128
            // point A
            float dot = fmaf(x0, p.x, fmaf(y0, p.y, z0 * p.z));
            float d2  = fmaxf(fmaf(-2.f, dot, w0 + p.w), 0.f);
            d2 = (m == n0) ? CUDART_INF_F : d2;
            float t0 = fmaxf(a0, d2);  a0 = fminf(a0, d2);
            float t1 = fmaxf(a1, t0);  a1 = fminf(a1, t0);
            a2 = fminf(a2, t1);
            // point B (lanes without a second point compute garbage, discarded)
            dot = fmaf(x1, p.x, fmaf(y1, p.y, z1 * p.z));
            d2  = fmaxf(fmaf(-2.f, dot, w1 + p.w), 0.f);
            d2 = (m == n1) ? CUDART_INF_F : d2;
            t0 = fmaxf(b0, d2);  b0 = fminf(b0, d2);
            t1 = fmaxf(b1, t0);  b1 = fminf(b1, t0);
            b2 = fminf(b2, t1);
        }
        float dn0 = (sqrtf(a0) + sqrtf(a1) + sqrtf(a2)) * (1.0f / 3.0f);
        s_cddn[wid][n0] = make_float2(cd0, dn0);
        if (has1) {
            float dn1 = (sqrtf(b0) + sqrtf(b1) + sqrtf(b2)) * (1.0f / 3.0f);
            s_cddn[wid][n1] = make_float2(cd1, dn1);
        }
        __syncwarp();
    }

    // ---- wait for precompute grid (overlapped with everything above) ----
    cudaGridDependencySynchronize();
    const float4 ru = reinterpret_cast<const float4*>(g_u)[lane];
    const float4 rv = reinterpret_cast<const float4*>(g_v)[lane];
    const float4 rc = reinterpret_cast<const float4*>(g_c)[lane];

    // ---- epilogue: 49 rows x 128 floats, lane stores its float4 column ----
    if (active) {
        float4* outp = reinterpret_cast<float4*>(out)
                     + (size_t)batch * (NPT * 32) + lane;
#pragma unroll 7
        for (int r = 0; r < NPT; r++) {
            float2 cddn = s_cddn[wid][r];            // broadcast LDS.64
            float4 o;
            o.x = fmaf(cddn.x, ru.x, fmaf(cddn.y, rv.x, rc.x));
            o.y = fmaf(cddn.x, ru.y, fmaf(cddn.y, rv.y, rc.y));
            o.z = fmaf(cddn.x, ru.z, fmaf(cddn.y, rv.z, rc.z));
            o.w = fmaf(cddn.x, ru.w, fmaf(cddn.y, rv.w, rc.w));
            __stcs(&outp[(size_t)r * 32], o);        // streaming: evict-first
        }
    }
}

extern "C" void kernel_launch(void* const* d_in, const int* in_sizes, int n_in,
                              void* d_out, int out_size) {
    const float* points = (const float*)d_in[0];
    const float* W_dist = (const float*)d_in[1];
    const float* b_dist = (const float*)d_in[2];
    const float* emb    = (const float*)d_in[3];
    const float* W_den  = (const float*)d_in[4];
    const float* b_den  = (const float*)d_in[5];
    const float* W_out  = (const float*)d_in[6];
    const float* b_out  = (const float*)d_in[7];
    float* out = (float*)d_out;

    int B = in_sizes[0] / (NPT * 3);
    int grid = (B + 7) / 8;

    precompute_uvc<<<1, 1024>>>(W_dist, b_dist, emb, W_den, b_den, W_out, b_out);

    cudaLaunchConfig_t cfg = {};
    cfg.gridDim  = dim3(grid, 1, 1);
    cfg.blockDim = dim3(256, 1, 1);
    cfg.dynamicSmemBytes = 0;
    cfg.stream = 0;
    cudaLaunchAttribute attrs[1];
    attrs[0].id = cudaLaunchAttributeProgrammaticStreamSerialization;
    attrs[0].val.programmaticStreamSerializationAllowed = 1;
    cfg.attrs = attrs;
    cfg.numAttrs = 1;

    cudaLaunchKernelEx(&cfg, nrpf_main, points, out, B);
}